// round 7
// baseline (speedup 1.0000x reference)
#include <cuda_runtime.h>
#include <cuda_fp16.h>
#include <cstdint>

// Problem constants
#define NUM_AUTHOR 16604
#define NUM_NODES  29059
#define DIM        300
#define NB         32768
#define NE         1048576

// GEMM shape: proj = emb[29059,300] @ Wcat[960,300]^T  (padded M=29184, K=320)
#define MPAD  29184        // 228 * 128
#define KA    320          // padded K for wcat rows
#define NPADC 960          // 3 sections x 320 cols
#define PSTR  960          // proj row stride (halves)

// Scratch (device globals; allocation-free rule)
__device__ float  g_wcat[(size_t)NPADC * KA];    // tf32-rounded, remapped W1
__device__ __half g_proj[(size_t)MPAD * PSTR];   // projected table, fp16 (56 MB)
__device__ float  g_rsB[DIM];                    // rowsum of Wb (empty-type-1 fallback)
__device__ float  g_rsC[DIM];                    // rowsum of Wc (empty-type-2 fallback)
__device__ int    g_off[NB + 1];

__device__ __forceinline__ float tf32r(float x) {
    uint32_t u;
    asm("cvt.rna.tf32.f32 %0, %1;" : "=r"(u) : "f"(x));
    return __uint_as_float(u);
}
__device__ __forceinline__ uint32_t tf32u(float x) {
    uint32_t u;
    asm("cvt.rna.tf32.f32 %0, %1;" : "=r"(u) : "f"(x));
    return u;
}

__device__ __forceinline__ void cp_async16(void* sdst, const void* gsrc) {
    uint32_t d = (uint32_t)__cvta_generic_to_shared(sdst);
    asm volatile("cp.async.cg.shared.global [%0], [%1], 16;" :: "r"(d), "l"(gsrc));
}
// zero-fill variant: copies src_size bytes (0 or 16), zero-fills the rest
__device__ __forceinline__ void cp_async16z(void* sdst, const void* gsrc, int sz) {
    uint32_t d = (uint32_t)__cvta_generic_to_shared(sdst);
    asm volatile("cp.async.cg.shared.global [%0], [%1], 16, %2;" :: "r"(d), "l"(gsrc), "r"(sz));
}
#define CP_COMMIT() asm volatile("cp.async.commit_group;")
#define CP_WAIT(n)  asm volatile("cp.async.wait_group %0;" :: "n"(n))

// ---------------------------------------------------------------------------
// Kernel 1: segment offsets via binary search (seg sorted)
// ---------------------------------------------------------------------------
__global__ void offsets_kernel(const int* __restrict__ seg) {
    int i = blockIdx.x * blockDim.x + threadIdx.x;
    if (i > NB) return;
    int lo = 0, hi = NE;
    while (lo < hi) {
        int mid = (lo + hi) >> 1;
        if (seg[mid] < i) lo = mid + 1; else hi = mid;
    }
    g_off[i] = lo;
}

// ---------------------------------------------------------------------------
// Kernel 2: build Wcat [960 x 320]: wcat[s*320+j][k] = tf32(W1[j][s*300+k])
// (rows j>=300 of each section are zero -> proj pad halves are exact zeros)
// ---------------------------------------------------------------------------
__global__ void wcat_kernel(const float* __restrict__ W1) {
    int c = blockIdx.x, k = threadIdx.x;       // grid=960, block=320
    int sec = c / 320, j = c - sec * 320;
    float v = 0.0f;
    if (j < DIM && k < DIM) v = tf32r(W1[(size_t)j * (3 * DIM) + sec * DIM + k]);
    g_wcat[(size_t)c * KA + k] = v;
}

// ---------------------------------------------------------------------------
// Kernel 3: parallel fallback rowsums
// ---------------------------------------------------------------------------
__global__ void rowsum_kernel(const float* __restrict__ W1) {
    int j = blockIdx.x;
    int w = threadIdx.x >> 5, lane = threadIdx.x & 31;
    const float* base = W1 + (size_t)j * (3 * DIM) + DIM + w * DIM;
    float s = 0.f;
    for (int k = lane; k < DIM; k += 32) s += base[k];
#pragma unroll
    for (int o = 16; o; o >>= 1) s += __shfl_xor_sync(0xffffffffu, s, o);
    if (lane == 0) {
        if (w == 0) g_rsB[j] = s; else g_rsC[j] = s;
    }
}

// ---------------------------------------------------------------------------
// Kernel 4: GEMM  proj[MPAD,960](fp16) = emb(padded) @ wcat^T
// tf32 mma m16n8k8; BM=128, BN=96, BK=32; 4 warps (2m x 2n), warp tile 64x48
// ---------------------------------------------------------------------------
#define BM 128
#define BN 96
#define BK 32
#define NT (KA / BK)       // 10
#define A_BUF (BM * BK)    // 4096 floats
#define B_BUF (BN * BK)    // 3072 floats
#define GEMM_SMEM ((2 * A_BUF + 2 * B_BUF) * 4)   // 57344 bytes

__device__ __forceinline__ void load_tiles(const float* __restrict__ emb,
                                           const float* __restrict__ Bg,
                                           float* sA, float* sB,
                                           int bmBase, int kt, int tid) {
    int colBase = kt * BK;
#pragma unroll
    for (int i = 0; i < 8; i++) {              // A: 128x32 = 1024 float4
        int lin = tid + i * 128;
        int row = lin >> 3, c4 = lin & 7;
        int gr  = bmBase + row;
        int col = colBase + c4 * 4;
        bool valid = (gr < NUM_NODES) && (col < DIM);
        const float* src = valid ? emb + (size_t)gr * DIM + col : emb;
        int scol = (c4 * 4) ^ ((row & 7) << 2);
        cp_async16z(&sA[row * BK + scol], src, valid ? 16 : 0);
    }
#pragma unroll
    for (int i = 0; i < 6; i++) {              // B: 96x32 = 768 float4
        int lin = tid + i * 128;
        int row = lin >> 3, c4 = lin & 7;
        int scol = (c4 * 4) ^ ((row & 7) << 2);
        cp_async16(&sB[row * BK + scol], Bg + (size_t)row * KA + colBase + c4 * 4);
    }
}

__global__ void __launch_bounds__(128) proj_gemm_kernel(const float* __restrict__ emb) {
    extern __shared__ float sm[];
    float* sA = sm;                 // [2][BM][BK]
    float* sB = sm + 2 * A_BUF;     // [2][BN][BK]

    int bn = blockIdx.x;      // 0..9
    int bm = blockIdx.y;      // 0..227
    int tid = threadIdx.x;
    int warp = tid >> 5, lane = tid & 31;
    int wm = warp & 1, wn = warp >> 1;
    int gid = lane >> 2, tig = lane & 3;

    int bmBase = bm * BM;
    const float* Bg = g_wcat + (size_t)(bn * BN) * KA;

    float c[4][6][4];
#pragma unroll
    for (int mt = 0; mt < 4; mt++)
#pragma unroll
        for (int nt = 0; nt < 6; nt++)
#pragma unroll
            for (int i = 0; i < 4; i++) c[mt][nt][i] = 0.f;

    load_tiles(emb, Bg, sA, sB, bmBase, 0, tid);
    CP_COMMIT();

    for (int kt = 0; kt < NT; kt++) {
        int buf = kt & 1;
        if (kt + 1 < NT) {
            load_tiles(emb, Bg, sA + (buf ^ 1) * A_BUF, sB + (buf ^ 1) * B_BUF,
                       bmBase, kt + 1, tid);
            CP_COMMIT();
            CP_WAIT(1);
        } else {
            CP_WAIT(0);
        }
        __syncthreads();

        const float* Ab = sA + buf * A_BUF;
        const float* Bb = sB + buf * B_BUF;

#pragma unroll
        for (int ks = 0; ks < 4; ks++) {
            int k0 = ks * 8;
            uint32_t a[4][4], bfr[6][2];
#pragma unroll
            for (int mt = 0; mt < 4; mt++) {
                int r0 = wm * 64 + mt * 16 + gid;
                int x = (r0 & 7) << 2;           // (r0+8)&7 == r0&7
                a[mt][0] = tf32u(Ab[r0 * BK + ((k0 + tig) ^ x)]);
                a[mt][1] = tf32u(Ab[(r0 + 8) * BK + ((k0 + tig) ^ x)]);
                a[mt][2] = tf32u(Ab[r0 * BK + ((k0 + tig + 4) ^ x)]);
                a[mt][3] = tf32u(Ab[(r0 + 8) * BK + ((k0 + tig + 4) ^ x)]);
            }
#pragma unroll
            for (int nt = 0; nt < 6; nt++) {
                int n = wn * 48 + nt * 8 + gid;
                int x = (n & 7) << 2;
                bfr[nt][0] = __float_as_uint(Bb[n * BK + ((k0 + tig) ^ x)]);
                bfr[nt][1] = __float_as_uint(Bb[n * BK + ((k0 + tig + 4) ^ x)]);
            }
#pragma unroll
            for (int mt = 0; mt < 4; mt++)
#pragma unroll
                for (int nt = 0; nt < 6; nt++) {
                    asm volatile(
                        "mma.sync.aligned.m16n8k8.row.col.f32.tf32.tf32.f32 "
                        "{%0,%1,%2,%3},{%4,%5,%6,%7},{%8,%9},{%0,%1,%2,%3};"
                        : "+f"(c[mt][nt][0]), "+f"(c[mt][nt][1]),
                          "+f"(c[mt][nt][2]), "+f"(c[mt][nt][3])
                        : "r"(a[mt][0]), "r"(a[mt][1]), "r"(a[mt][2]), "r"(a[mt][3]),
                          "r"(bfr[nt][0]), "r"(bfr[nt][1]));
                }
        }
        __syncthreads();
    }

    // Epilogue: fp16 store (bias added later in agg)
#pragma unroll
    for (int mt = 0; mt < 4; mt++) {
#pragma unroll
        for (int nt = 0; nt < 6; nt++) {
            int gm = bmBase + wm * 64 + mt * 16 + gid;
            int gn = bn * BN + wn * 48 + nt * 8 + tig * 2;
            __half2 h0 = __floats2half2_rn(c[mt][nt][0], c[mt][nt][1]);
            __half2 h1 = __floats2half2_rn(c[mt][nt][2], c[mt][nt][3]);
            *(__half2*)(g_proj + (size_t)gm * PSTR + gn) = h0;
            *(__half2*)(g_proj + (size_t)(gm + 8) * PSTR + gn) = h1;
        }
    }
}

// ---------------------------------------------------------------------------
// Kernel 5: aggregation, uint4 gathers, 4 edge-groups x 40 threads
// group g processes edges e = start+g, start+g+4, ...; lane l covers halves
// [l*8, l*8+8) of the 320-half section (pads are exact zeros).
// Cross-group partial sums merged via smem, then final output.
// ---------------------------------------------------------------------------
#define GRP  40
#define NGRP 4

__global__ void __launch_bounds__(GRP * NGRP) agg_kernel(
    const int* __restrict__ nodes,
    const int* __restrict__ neighbors,
    const float* __restrict__ b1,
    float* __restrict__ out)
{
    __shared__ float s_a1[NGRP][GRP * 8];   // 5120 B
    __shared__ float s_a2[NGRP][GRP * 8];   // 5120 B
    __shared__ int   s_c1[NGRP];

    int b   = blockIdx.x;
    int tid = threadIdx.x;
    int g   = tid / GRP;
    int l   = tid - g * GRP;
    int start = g_off[b];
    int end   = g_off[b + 1];
    int node  = nodes[b];
    bool selfA = node < NUM_AUTHOR;

    float2 a1[4], a2[4];
#pragma unroll
    for (int j = 0; j < 4; j++) { a1[j] = make_float2(0.f, 0.f); a2[j] = make_float2(0.f, 0.f); }
    int c1 = 0;

    // edge loop with next-index prefetch
    int e = start + g;
    int n_next = (e < end) ? neighbors[e] : 0;
    while (e < end) {
        int n = n_next;
        int e2 = e + NGRP;
        if (e2 < end) n_next = neighbors[e2];
        bool s = (n < NUM_AUTHOR) == selfA;
        const uint4* p = (const uint4*)(g_proj + (size_t)n * PSTR + (s ? 320 : 640)) + l;
        uint4 v = *p;
        const __half2* hv = (const __half2*)&v;
        float2 f0 = __half22float2(hv[0]);
        float2 f1 = __half22float2(hv[1]);
        float2 f2 = __half22float2(hv[2]);
        float2 f3 = __half22float2(hv[3]);
        if (s) {
            a1[0].x += f0.x; a1[0].y += f0.y;
            a1[1].x += f1.x; a1[1].y += f1.y;
            a1[2].x += f2.x; a1[2].y += f2.y;
            a1[3].x += f3.x; a1[3].y += f3.y;
            c1++;
        } else {
            a2[0].x += f0.x; a2[0].y += f0.y;
            a2[1].x += f1.x; a2[1].y += f1.y;
            a2[2].x += f2.x; a2[2].y += f2.y;
            a2[3].x += f3.x; a2[3].y += f3.y;
        }
        e = e2;
    }

    // write partial sums
#pragma unroll
    for (int j = 0; j < 4; j++) {
        *(float2*)&s_a1[g][l * 8 + j * 2] = a1[j];
        *(float2*)&s_a2[g][l * 8 + j * 2] = a2[j];
    }
    if (l == 0) s_c1[g] = c1;
    __syncthreads();

    // final: threads 0..39, each covers dims [tid*8, tid*8+8)
    if (tid < GRP) {
        int c1t = s_c1[0] + s_c1[1] + s_c1[2] + s_c1[3];
        int tot = end - start;
        int c2t = tot - c1t;
        float r1 = (c1t > 0) ? 1.0f / (float)c1t : 0.f;
        float r2 = (c2t > 0) ? 1.0f / (float)c2t : 0.f;

        uint4 sv = *((const uint4*)(g_proj + (size_t)node * PSTR) + tid);
        const __half2* shv = (const __half2*)&sv;

#pragma unroll
        for (int j = 0; j < 4; j++) {
            float2 sf = __half22float2(shv[j]);
            int d0 = tid * 8 + j * 2;
#pragma unroll
            for (int q = 0; q < 2; q++) {
                int d = d0 + q;
                if (d < DIM) {
                    float sum1 = s_a1[0][tid * 8 + j * 2 + q] + s_a1[1][tid * 8 + j * 2 + q]
                               + s_a1[2][tid * 8 + j * 2 + q] + s_a1[3][tid * 8 + j * 2 + q];
                    float sum2 = s_a2[0][tid * 8 + j * 2 + q] + s_a2[1][tid * 8 + j * 2 + q]
                               + s_a2[2][tid * 8 + j * 2 + q] + s_a2[3][tid * 8 + j * 2 + q];
                    float t1 = (c1t > 0) ? sum1 * r1 : g_rsB[d];
                    float t2 = (c2t > 0) ? sum2 * r2 : g_rsC[d];
                    float sfv = (q == 0) ? sf.x : sf.y;
                    out[(size_t)b * DIM + d] = sfv + t1 + t2 + b1[d];
                }
            }
        }
    }
}

// ---------------------------------------------------------------------------
extern "C" void kernel_launch(void* const* d_in, const int* in_sizes, int n_in,
                              void* d_out, int out_size) {
    const int*   nodes     = (const int*)d_in[0];
    const int*   seg       = (const int*)d_in[1];
    const int*   neighbors = (const int*)d_in[2];
    const float* emb       = (const float*)d_in[3];
    const float* W1        = (const float*)d_in[4];
    const float* b1        = (const float*)d_in[5];
    float*       out       = (float*)d_out;

    cudaFuncSetAttribute(proj_gemm_kernel,
                         cudaFuncAttributeMaxDynamicSharedMemorySize, GEMM_SMEM);

    offsets_kernel<<<(NB + 1 + 255) / 256, 256>>>(seg);
    wcat_kernel<<<NPADC, 320>>>(W1);
    rowsum_kernel<<<DIM, 64>>>(W1);
    dim3 ggrid(NPADC / BN, MPAD / BM);   // (10, 228), x-fast shares A via L2
    proj_gemm_kernel<<<ggrid, 128, GEMM_SMEM>>>(emb);
    agg_kernel<<<NB, GRP * NGRP>>>(nodes, neighbors, b1, out);
}

// round 8
// speedup vs baseline: 1.2124x; 1.2124x over previous
#include <cuda_runtime.h>
#include <cuda_fp16.h>
#include <cstdint>

// Problem constants
#define NUM_AUTHOR 16604
#define NUM_NODES  29059
#define DIM        300
#define NB         32768
#define NE         1048576

// GEMM shape: proj = emb[29059,300] @ Wcat[960,300]^T  (padded M=29184, K=320)
#define MPAD  29184        // 228 * 128
#define KA    320          // padded K for wcat rows
#define NPADC 960          // 3 sections x 320 cols
#define PSTR  960          // proj row stride (halves)

// Scratch (device globals; allocation-free rule)
__device__ float  g_wcat[(size_t)NPADC * KA];    // tf32-rounded, remapped W1
__device__ __half g_proj[(size_t)MPAD * PSTR];   // projected table, fp16 (56 MB)
__device__ float  g_rsB[DIM];                    // rowsum of Wb (empty-type-1 fallback)
__device__ float  g_rsC[DIM];                    // rowsum of Wc (empty-type-2 fallback)
__device__ int    g_off[NB + 1];

__device__ __forceinline__ float tf32r(float x) {
    uint32_t u;
    asm("cvt.rna.tf32.f32 %0, %1;" : "=r"(u) : "f"(x));
    return __uint_as_float(u);
}
__device__ __forceinline__ uint32_t tf32u(float x) {
    uint32_t u;
    asm("cvt.rna.tf32.f32 %0, %1;" : "=r"(u) : "f"(x));
    return u;
}

__device__ __forceinline__ void cp_async16(void* sdst, const void* gsrc) {
    uint32_t d = (uint32_t)__cvta_generic_to_shared(sdst);
    asm volatile("cp.async.cg.shared.global [%0], [%1], 16;" :: "r"(d), "l"(gsrc));
}
// zero-fill variant: copies src_size bytes (0 or 16), zero-fills the rest
__device__ __forceinline__ void cp_async16z(void* sdst, const void* gsrc, int sz) {
    uint32_t d = (uint32_t)__cvta_generic_to_shared(sdst);
    asm volatile("cp.async.cg.shared.global [%0], [%1], 16, %2;" :: "r"(d), "l"(gsrc), "r"(sz));
}
#define CP_COMMIT() asm volatile("cp.async.commit_group;")
#define CP_WAIT(n)  asm volatile("cp.async.wait_group %0;" :: "n"(n))

// ---------------------------------------------------------------------------
// Kernel 1: segment offsets via binary search (seg sorted)
// ---------------------------------------------------------------------------
__global__ void offsets_kernel(const int* __restrict__ seg) {
    int i = blockIdx.x * blockDim.x + threadIdx.x;
    if (i > NB) return;
    int lo = 0, hi = NE;
    while (lo < hi) {
        int mid = (lo + hi) >> 1;
        if (seg[mid] < i) lo = mid + 1; else hi = mid;
    }
    g_off[i] = lo;
}

// ---------------------------------------------------------------------------
// Kernel 2: build Wcat [960 x 320]: wcat[s*320+j][k] = tf32(W1[j][s*300+k])
// (rows j>=300 of each section are zero -> proj pad halves are exact zeros)
// ---------------------------------------------------------------------------
__global__ void wcat_kernel(const float* __restrict__ W1) {
    int c = blockIdx.x, k = threadIdx.x;       // grid=960, block=320
    int sec = c / 320, j = c - sec * 320;
    float v = 0.0f;
    if (j < DIM && k < DIM) v = tf32r(W1[(size_t)j * (3 * DIM) + sec * DIM + k]);
    g_wcat[(size_t)c * KA + k] = v;
}

// ---------------------------------------------------------------------------
// Kernel 3: parallel fallback rowsums
// ---------------------------------------------------------------------------
__global__ void rowsum_kernel(const float* __restrict__ W1) {
    int j = blockIdx.x;
    int w = threadIdx.x >> 5, lane = threadIdx.x & 31;
    const float* base = W1 + (size_t)j * (3 * DIM) + DIM + w * DIM;
    float s = 0.f;
    for (int k = lane; k < DIM; k += 32) s += base[k];
#pragma unroll
    for (int o = 16; o; o >>= 1) s += __shfl_xor_sync(0xffffffffu, s, o);
    if (lane == 0) {
        if (w == 0) g_rsB[j] = s; else g_rsC[j] = s;
    }
}

// ---------------------------------------------------------------------------
// Kernel 4: GEMM  proj[MPAD,960](fp16) = emb(padded) @ wcat^T
// tf32 mma m16n8k8; BM=128, BN=96, BK=32; 4 warps (2m x 2n), warp tile 64x48
// ---------------------------------------------------------------------------
#define BM 128
#define BN 96
#define BK 32
#define NT (KA / BK)       // 10
#define A_BUF (BM * BK)    // 4096 floats
#define B_BUF (BN * BK)    // 3072 floats
#define GEMM_SMEM ((2 * A_BUF + 2 * B_BUF) * 4)   // 57344 bytes

__device__ __forceinline__ void load_tiles(const float* __restrict__ emb,
                                           const float* __restrict__ Bg,
                                           float* sA, float* sB,
                                           int bmBase, int kt, int tid) {
    int colBase = kt * BK;
#pragma unroll
    for (int i = 0; i < 8; i++) {              // A: 128x32 = 1024 float4
        int lin = tid + i * 128;
        int row = lin >> 3, c4 = lin & 7;
        int gr  = bmBase + row;
        int col = colBase + c4 * 4;
        bool valid = (gr < NUM_NODES) && (col < DIM);
        const float* src = valid ? emb + (size_t)gr * DIM + col : emb;
        int scol = (c4 * 4) ^ ((row & 7) << 2);
        cp_async16z(&sA[row * BK + scol], src, valid ? 16 : 0);
    }
#pragma unroll
    for (int i = 0; i < 6; i++) {              // B: 96x32 = 768 float4
        int lin = tid + i * 128;
        int row = lin >> 3, c4 = lin & 7;
        int scol = (c4 * 4) ^ ((row & 7) << 2);
        cp_async16(&sB[row * BK + scol], Bg + (size_t)row * KA + colBase + c4 * 4);
    }
}

__global__ void __launch_bounds__(128) proj_gemm_kernel(const float* __restrict__ emb) {
    extern __shared__ float sm[];
    float* sA = sm;                 // [2][BM][BK]
    float* sB = sm + 2 * A_BUF;     // [2][BN][BK]

    int bn = blockIdx.x;      // 0..9
    int bm = blockIdx.y;      // 0..227
    int tid = threadIdx.x;
    int warp = tid >> 5, lane = tid & 31;
    int wm = warp & 1, wn = warp >> 1;
    int gid = lane >> 2, tig = lane & 3;

    int bmBase = bm * BM;
    const float* Bg = g_wcat + (size_t)(bn * BN) * KA;

    float c[4][6][4];
#pragma unroll
    for (int mt = 0; mt < 4; mt++)
#pragma unroll
        for (int nt = 0; nt < 6; nt++)
#pragma unroll
            for (int i = 0; i < 4; i++) c[mt][nt][i] = 0.f;

    load_tiles(emb, Bg, sA, sB, bmBase, 0, tid);
    CP_COMMIT();

    for (int kt = 0; kt < NT; kt++) {
        int buf = kt & 1;
        if (kt + 1 < NT) {
            load_tiles(emb, Bg, sA + (buf ^ 1) * A_BUF, sB + (buf ^ 1) * B_BUF,
                       bmBase, kt + 1, tid);
            CP_COMMIT();
            CP_WAIT(1);
        } else {
            CP_WAIT(0);
        }
        __syncthreads();

        const float* Ab = sA + buf * A_BUF;
        const float* Bb = sB + buf * B_BUF;

#pragma unroll
        for (int ks = 0; ks < 4; ks++) {
            int k0 = ks * 8;
            uint32_t a[4][4], bfr[6][2];
#pragma unroll
            for (int mt = 0; mt < 4; mt++) {
                int r0 = wm * 64 + mt * 16 + gid;
                int x = (r0 & 7) << 2;           // (r0+8)&7 == r0&7
                a[mt][0] = tf32u(Ab[r0 * BK + ((k0 + tig) ^ x)]);
                a[mt][1] = tf32u(Ab[(r0 + 8) * BK + ((k0 + tig) ^ x)]);
                a[mt][2] = tf32u(Ab[r0 * BK + ((k0 + tig + 4) ^ x)]);
                a[mt][3] = tf32u(Ab[(r0 + 8) * BK + ((k0 + tig + 4) ^ x)]);
            }
#pragma unroll
            for (int nt = 0; nt < 6; nt++) {
                int n = wn * 48 + nt * 8 + gid;
                int x = (n & 7) << 2;
                bfr[nt][0] = __float_as_uint(Bb[n * BK + ((k0 + tig) ^ x)]);
                bfr[nt][1] = __float_as_uint(Bb[n * BK + ((k0 + tig + 4) ^ x)]);
            }
#pragma unroll
            for (int mt = 0; mt < 4; mt++)
#pragma unroll
                for (int nt = 0; nt < 6; nt++) {
                    asm volatile(
                        "mma.sync.aligned.m16n8k8.row.col.f32.tf32.tf32.f32 "
                        "{%0,%1,%2,%3},{%4,%5,%6,%7},{%8,%9},{%0,%1,%2,%3};"
                        : "+f"(c[mt][nt][0]), "+f"(c[mt][nt][1]),
                          "+f"(c[mt][nt][2]), "+f"(c[mt][nt][3])
                        : "r"(a[mt][0]), "r"(a[mt][1]), "r"(a[mt][2]), "r"(a[mt][3]),
                          "r"(bfr[nt][0]), "r"(bfr[nt][1]));
                }
        }
        __syncthreads();
    }

    // Epilogue: fp16 store (bias added later in agg)
#pragma unroll
    for (int mt = 0; mt < 4; mt++) {
#pragma unroll
        for (int nt = 0; nt < 6; nt++) {
            int gm = bmBase + wm * 64 + mt * 16 + gid;
            int gn = bn * BN + wn * 48 + nt * 8 + tig * 2;
            __half2 h0 = __floats2half2_rn(c[mt][nt][0], c[mt][nt][1]);
            __half2 h1 = __floats2half2_rn(c[mt][nt][2], c[mt][nt][3]);
            *(__half2*)(g_proj + (size_t)gm * PSTR + gn) = h0;
            *(__half2*)(g_proj + (size_t)(gm + 8) * PSTR + gn) = h1;
        }
    }
}

// ---------------------------------------------------------------------------
// Kernel 5: aggregation (R6 structure: block = node, thread = half2 slot,
// edges block-uniform so type-branch is warp-uniform).
// NEW: 16-edge chunks accumulated in fp16 (__hadd2, 1 instr/edge), flushed
// to fp32 per chunk; 16 independent gathers in flight (MLP=16).
// ---------------------------------------------------------------------------
#define CHUNK 16

__global__ void __launch_bounds__(160) agg_kernel(
    const int* __restrict__ nodes,
    const int* __restrict__ neighbors,
    const float* __restrict__ b1,
    float* __restrict__ out)
{
    int b = blockIdx.x;
    int tid = threadIdx.x;
    int start = g_off[b];
    int end   = g_off[b + 1];
    int node  = nodes[b];
    bool selfA = node < NUM_AUTHOR;

    float2 a1 = {0.f, 0.f}, a2 = {0.f, 0.f};
    int c1 = 0;
    const __half2 z2 = __float2half2_rn(0.f);

    int e = start;
    for (; e + CHUNK <= end; e += CHUNK) {
        int  nn[CHUNK];
        bool ss[CHUNK];
        __half2 h[CHUNK];
#pragma unroll
        for (int j = 0; j < CHUNK; j++) nn[j] = neighbors[e + j];
#pragma unroll
        for (int j = 0; j < CHUNK; j++) {
            ss[j] = (nn[j] < NUM_AUTHOR) == selfA;
            h[j] = *((const __half2*)(g_proj + (size_t)nn[j] * PSTR + (ss[j] ? 320 : 640)) + tid);
        }
        __half2 p1 = z2, p2 = z2;
#pragma unroll
        for (int j = 0; j < CHUNK; j++) {
            if (ss[j]) { p1 = __hadd2(p1, h[j]); c1++; }
            else       { p2 = __hadd2(p2, h[j]); }
        }
        float2 f1 = __half22float2(p1);
        float2 f2 = __half22float2(p2);
        a1.x += f1.x; a1.y += f1.y;
        a2.x += f2.x; a2.y += f2.y;
    }
    // remainder (< CHUNK edges), same fp16 partial then single flush
    {
        __half2 p1 = z2, p2 = z2;
        for (; e < end; e++) {
            int n = neighbors[e];
            bool s = (n < NUM_AUTHOR) == selfA;
            __half2 h = *((const __half2*)(g_proj + (size_t)n * PSTR + (s ? 320 : 640)) + tid);
            if (s) { p1 = __hadd2(p1, h); c1++; }
            else   { p2 = __hadd2(p2, h); }
        }
        float2 f1 = __half22float2(p1);
        float2 f2 = __half22float2(p2);
        a1.x += f1.x; a1.y += f1.y;
        a2.x += f2.x; a2.y += f2.y;
    }

    if (tid * 2 < DIM) {
        int tot = end - start;
        int c2 = tot - c1;
        float2 t1, t2;
        if (c1 > 0) { float r = 1.0f / (float)c1; t1.x = a1.x * r; t1.y = a1.y * r; }
        else        { t1.x = g_rsB[2 * tid];      t1.y = g_rsB[2 * tid + 1]; }
        if (c2 > 0) { float r = 1.0f / (float)c2; t2.x = a2.x * r; t2.y = a2.y * r; }
        else        { t2.x = g_rsC[2 * tid];      t2.y = g_rsC[2 * tid + 1]; }

        __half2 sh = *((const __half2*)(g_proj + (size_t)node * PSTR) + tid);
        float2 sf = __half22float2(sh);
        float2 bb = *(const float2*)(b1 + 2 * tid);
        float2 o;
        o.x = sf.x + t1.x + t2.x + bb.x;
        o.y = sf.y + t1.y + t2.y + bb.y;
        *(float2*)(out + (size_t)b * DIM + 2 * tid) = o;
    }
}

// ---------------------------------------------------------------------------
extern "C" void kernel_launch(void* const* d_in, const int* in_sizes, int n_in,
                              void* d_out, int out_size) {
    const int*   nodes     = (const int*)d_in[0];
    const int*   seg       = (const int*)d_in[1];
    const int*   neighbors = (const int*)d_in[2];
    const float* emb       = (const float*)d_in[3];
    const float* W1        = (const float*)d_in[4];
    const float* b1        = (const float*)d_in[5];
    float*       out       = (float*)d_out;

    cudaFuncSetAttribute(proj_gemm_kernel,
                         cudaFuncAttributeMaxDynamicSharedMemorySize, GEMM_SMEM);

    offsets_kernel<<<(NB + 1 + 255) / 256, 256>>>(seg);
    wcat_kernel<<<NPADC, 320>>>(W1);
    rowsum_kernel<<<DIM, 64>>>(W1);
    dim3 ggrid(NPADC / BN, MPAD / BM);   // (10, 228), x-fast shares A via L2
    proj_gemm_kernel<<<ggrid, 128, GEMM_SMEM>>>(emb);
    agg_kernel<<<NB, 160>>>(nodes, neighbors, b1, out);
}